// round 13
// baseline (speedup 1.0000x reference)
#include <cuda_runtime.h>
#include <cuda_bf16.h>
#include <cstdint>

#define N_NODES 16384
#define E_RAW   262144
#define E_TOT   (E_RAW + N_NODES)   // 278528 with self loops
#define H1      256
#define D2      512                  // 2*H1 = gat1 out channels = gat2 channels

// ---------------- scratch (device globals; no allocation allowed) -------------
__device__ float g_h0  [N_NODES * H1];   // fc output (relu, tf32-rounded)
__device__ float g_g1  [N_NODES * D2];   // gat1 pre-agg features
__device__ float g_out1[N_NODES * D2];   // gat1 output (relu, tf32-rounded)
__device__ float g_g2  [N_NODES * D2];   // gat2 pre-agg features
__device__ float g_xr  [N_NODES * H1];   // tf32-rounded x
__device__ float g_wfcr[H1 * H1];        // tf32-rounded W_fc
__device__ float g_w1r [H1 * D2];        // tf32-rounded W1
__device__ float g_w2r [D2 * D2];        // tf32-rounded W2
__device__ float g_al1s[N_NODES * 2];
__device__ float g_al1d[N_NODES * 2];
__device__ float g_al2s[N_NODES];
__device__ float g_al2d[N_NODES];
__device__ int   g_deg [N_NODES];
__device__ int   g_cur [N_NODES];
__device__ int   g_off [N_NODES + 1];
__device__ int   g_esrc[E_TOT];

__device__ __forceinline__ float* buf_sel(int id) {
    switch (id) {
        case 0: return g_h0;
        case 1: return g_g1;
        case 2: return g_out1;
        case 3: return g_g2;
        case 4: return g_xr;
        case 5: return g_wfcr;
        case 6: return g_w1r;
        case 7: return g_w2r;
    }
    return nullptr;
}

__device__ __forceinline__ float f2tf32f(float x) {
    uint32_t u;
    asm("cvt.rna.tf32.f32 %0, %1;" : "=r"(u) : "f"(x));
    return __uint_as_float(u);
}

// ------------------------------- CSR build -----------------------------------
__global__ void zero_kernel() {
    int i = blockIdx.x * blockDim.x + threadIdx.x;
    if (i < N_NODES) {
        g_deg[i] = 0; g_cur[i] = 0;
        g_al1s[2 * i] = 0.f; g_al1s[2 * i + 1] = 0.f;
        g_al1d[2 * i] = 0.f; g_al1d[2 * i + 1] = 0.f;
        g_al2s[i] = 0.f;     g_al2d[i] = 0.f;
    }
}

// adj is int32: adj[0..E_RAW) = src, adj[E_RAW..2*E_RAW) = dst
__global__ void hist_kernel(const int* __restrict__ adj) {
    int i0 = (blockIdx.x * blockDim.x + threadIdx.x) * 4;
    if (i0 >= E_TOT) return;
    int d[4];
#pragma unroll
    for (int j = 0; j < 4; j++) {
        int i = i0 + j;
        d[j] = (i < E_TOT) ? ((i < E_RAW) ? adj[E_RAW + i] : (i - E_RAW)) : -1;
    }
#pragma unroll
    for (int j = 0; j < 4; j++)
        if (d[j] >= 0) atomicAdd(&g_deg[d[j]], 1);
}

__global__ void scan_kernel() {
    __shared__ int partial[1024];
    int t = threadIdx.x;
    int base = t * 16;
    int local[16];
    int s = 0;
#pragma unroll
    for (int i = 0; i < 16; i++) { local[i] = s; s += g_deg[base + i]; }
    partial[t] = s;
    __syncthreads();
    for (int off = 1; off < 1024; off <<= 1) {
        int v = (t >= off) ? partial[t - off] : 0;
        __syncthreads();
        partial[t] += v;
        __syncthreads();
    }
    int pre = (t == 0) ? 0 : partial[t - 1];
#pragma unroll
    for (int i = 0; i < 16; i++) g_off[base + i] = pre + local[i];
    if (t == 1023) g_off[N_NODES] = partial[1023];
}

__global__ void scatter_kernel(const int* __restrict__ adj) {
    int i0 = (blockIdx.x * blockDim.x + threadIdx.x) * 4;
    if (i0 >= E_TOT) return;
    int sv[4], dv[4];
#pragma unroll
    for (int j = 0; j < 4; j++) {
        int i = i0 + j;
        if (i >= E_TOT)      { sv[j] = -1; dv[j] = -1; }
        else if (i < E_RAW)  { sv[j] = adj[i]; dv[j] = adj[E_RAW + i]; }
        else                 { sv[j] = i - E_RAW; dv[j] = i - E_RAW; }
    }
#pragma unroll
    for (int j = 0; j < 4; j++) {
        if (dv[j] >= 0) {
            int pos = g_off[dv[j]] + atomicAdd(&g_cur[dv[j]], 1);
            g_esrc[pos] = sv[j];
        }
    }
}

// --------------------------- tf32 pre-rounding --------------------------------
__global__ void round_copy(const float* __restrict__ src, int dst_sel, int n4) {
    float* dst = buf_sel(dst_sel);
    int i = blockIdx.x * blockDim.x + threadIdx.x;
    if (i >= n4) return;
    float4 v = ((const float4*)src)[i];
    v.x = f2tf32f(v.x); v.y = f2tf32f(v.y);
    v.z = f2tf32f(v.z); v.w = f2tf32f(v.w);
    ((float4*)dst)[i] = v;
}

// --------------------------- TF32 tensor-core GEMM ----------------------------
// C[M,N] = A[M,K] * B[K,N], row-major, inputs pre-rounded to tf32.
// CTA tile 128x128, 8 warps, warp tile 64x32, mma.sync m16n8k8 tf32.
// cp.async 2-stage double buffer, K-chunk 16.
// AL_MODE 1: fused gat1 logit partials (2 heads). AL_MODE 2: gat2 (1 head).
#define AS_STRIDE 20
#define BS_STRIDE 136

__device__ __forceinline__ uint32_t smem_u32(const void* p) {
    return (uint32_t)__cvta_generic_to_shared(p);
}
__device__ __forceinline__ void cp16(uint32_t dst, const void* src) {
    asm volatile("cp.async.cg.shared.global [%0], [%1], 16;"
                 :: "r"(dst), "l"(src));
}
__device__ __forceinline__ void cp_commit() {
    asm volatile("cp.async.commit_group;");
}
template <int NN> __device__ __forceinline__ void cp_wait() {
    asm volatile("cp.async.wait_group %0;" :: "n"(NN));
}

template <int RELU_BIAS, int AL_MODE, int ROUND_OUT>
__global__ __launch_bounds__(256) void gemm_tf32(
    int a_sel, int b_sel,
    const float* __restrict__ bias, int c_sel,
    const float* __restrict__ a_s, const float* __restrict__ a_d,
    int M, int N, int K)
{
    const float* A = buf_sel(a_sel);
    const float* B = buf_sel(b_sel);
    float* C = buf_sel(c_sel);

    __shared__ float As[2][128 * AS_STRIDE];   // [m][k16] pad->20
    __shared__ float Bs[2][16 * BS_STRIDE];    // [k16][n128] pad->136

    const int tid  = threadIdx.x;
    const int lane = tid & 31;
    const int wid  = tid >> 5;
    const int q = lane >> 2;     // 0..7
    const int r = lane & 3;      // 0..3
    const int wm = (wid >> 2) * 64;
    const int wn = (wid & 3) * 32;

    const int mBase = blockIdx.y * 128, nBase = blockIdx.x * 128;

    // per-thread cp.async coords
    const int arow = tid >> 2, ac4 = tid & 3;   // + l*64 rows
    const int bkk  = tid >> 5, bn4 = tid & 31;  // + l*8 k-rows

    float c[4][4][4];
#pragma unroll
    for (int i = 0; i < 4; i++)
#pragma unroll
        for (int j = 0; j < 4; j++)
#pragma unroll
            for (int u = 0; u < 4; u++) c[i][j][u] = 0.f;

    auto load_stage = [&](int buf, int k0) {
#pragma unroll
        for (int l = 0; l < 2; l++) {
            int row = arow + l * 64;
            cp16(smem_u32(&As[buf][row * AS_STRIDE + ac4 * 4]),
                 &A[(size_t)(mBase + row) * K + k0 + ac4 * 4]);
            int kk = bkk + l * 8;
            cp16(smem_u32(&Bs[buf][kk * BS_STRIDE + bn4 * 4]),
                 &B[(size_t)(k0 + kk) * N + nBase + bn4 * 4]);
        }
    };

    const int nch = K >> 4;
    load_stage(0, 0);  cp_commit();
    load_stage(1, 16); cp_commit();

    for (int ch = 0; ch < nch; ch++) {
        if (ch + 2 < nch) cp_wait<1>(); else cp_wait<0>();
        __syncthreads();
        const float* as = As[ch & 1];
        const float* bs = Bs[ch & 1];
#pragma unroll
        for (int kk8 = 0; kk8 < 2; kk8++) {
            const int kb = kk8 * 8;
            uint32_t a[4][4], b[4][2];
#pragma unroll
            for (int i = 0; i < 4; i++) {
                int row = wm + i * 16 + q;
                a[i][0] = __float_as_uint(as[(row)     * AS_STRIDE + kb + r]);
                a[i][1] = __float_as_uint(as[(row + 8) * AS_STRIDE + kb + r]);
                a[i][2] = __float_as_uint(as[(row)     * AS_STRIDE + kb + r + 4]);
                a[i][3] = __float_as_uint(as[(row + 8) * AS_STRIDE + kb + r + 4]);
            }
#pragma unroll
            for (int j = 0; j < 4; j++) {
                int col = wn + j * 8 + q;
                b[j][0] = __float_as_uint(bs[(kb + r)     * BS_STRIDE + col]);
                b[j][1] = __float_as_uint(bs[(kb + r + 4) * BS_STRIDE + col]);
            }
#pragma unroll
            for (int i = 0; i < 4; i++)
#pragma unroll
                for (int j = 0; j < 4; j++) {
                    asm volatile(
                        "mma.sync.aligned.m16n8k8.row.col.f32.tf32.tf32.f32 "
                        "{%0,%1,%2,%3}, {%4,%5,%6,%7}, {%8,%9}, {%0,%1,%2,%3};"
                        : "+f"(c[i][j][0]), "+f"(c[i][j][1]),
                          "+f"(c[i][j][2]), "+f"(c[i][j][3])
                        : "r"(a[i][0]), "r"(a[i][1]), "r"(a[i][2]), "r"(a[i][3]),
                          "r"(b[j][0]), "r"(b[j][1]));
                }
        }
        __syncthreads();
        if (ch + 2 < nch) { load_stage(ch & 1, (ch + 2) << 4); cp_commit(); }
    }

    // epilogue (+ optional fused attention-logit partial sums)
    float ps[4][2], pd[4][2];
    if (AL_MODE) {
#pragma unroll
        for (int i = 0; i < 4; i++) {
            ps[i][0] = ps[i][1] = 0.f;
            pd[i][0] = pd[i][1] = 0.f;
        }
    }

#pragma unroll
    for (int i = 0; i < 4; i++) {
        int row0 = mBase + wm + i * 16 + q;
#pragma unroll
        for (int j = 0; j < 4; j++) {
            int col = nBase + wn + j * 8 + 2 * r;
            float v0 = c[i][j][0], v1 = c[i][j][1];
            float v2 = c[i][j][2], v3 = c[i][j][3];
            if (RELU_BIAS) {
                float bb0 = bias[col], bb1 = bias[col + 1];
                v0 += bb0; v1 += bb1; v2 += bb0; v3 += bb1;
                v0 = v0 > 0.f ? v0 : 0.f; v1 = v1 > 0.f ? v1 : 0.f;
                v2 = v2 > 0.f ? v2 : 0.f; v3 = v3 > 0.f ? v3 : 0.f;
            }
            if (AL_MODE) {
                float as0 = a_s[col], as1 = a_s[col + 1];
                float ad0 = a_d[col], ad1 = a_d[col + 1];
                ps[i][0] += v0 * as0 + v1 * as1;
                pd[i][0] += v0 * ad0 + v1 * ad1;
                ps[i][1] += v2 * as0 + v3 * as1;
                pd[i][1] += v2 * ad0 + v3 * ad1;
            }
            if (ROUND_OUT) {
                v0 = f2tf32f(v0); v1 = f2tf32f(v1);
                v2 = f2tf32f(v2); v3 = f2tf32f(v3);
            }
            *(float2*)&C[(size_t)row0 * N + col]       = make_float2(v0, v1);
            *(float2*)&C[(size_t)(row0 + 8) * N + col] = make_float2(v2, v3);
        }
    }

    if (AL_MODE) {
#pragma unroll
        for (int i = 0; i < 4; i++) {
#pragma unroll
            for (int half = 0; half < 2; half++) {
                float s = ps[i][half], dd = pd[i][half];
                s  += __shfl_xor_sync(0xffffffffu, s, 1);
                s  += __shfl_xor_sync(0xffffffffu, s, 2);
                dd += __shfl_xor_sync(0xffffffffu, dd, 1);
                dd += __shfl_xor_sync(0xffffffffu, dd, 2);
                if (r == 0) {
                    int row = mBase + wm + i * 16 + q + half * 8;
                    if (AL_MODE == 1) {
                        int head = ((nBase + wn) >> 8) & 1;
                        atomicAdd(&g_al1s[row * 2 + head], s);
                        atomicAdd(&g_al1d[row * 2 + head], dd);
                    } else {
                        atomicAdd(&g_al2s[row], s);
                        atomicAdd(&g_al2d[row], dd);
                    }
                }
            }
        }
    }
}

// --------------------------- GAT aggregation ----------------------------------
// Softmax without max subtraction: self-loops guarantee nonempty segments and
// glorot-scale logits are O(+-5) -> exp cannot overflow; alpha identical.
// One CTA (256 threads) per dst node; thread t owns channels 2t, 2t+1.
__global__ void gat1_agg(const float* __restrict__ bias)  // b1[512] -> g_out1
{
    const float* h = g_g1;
    float* out = g_out1;
    int d = blockIdx.x, t = threadIdx.x;
    __shared__ float sw0[256], sw1[256];
    __shared__ int   ss[256];
    int start = g_off[d], end = g_off[d + 1];
    float ad0 = g_al1d[d * 2 + 0], ad1 = g_al1d[d * 2 + 1];
    float accx = 0.f, accy = 0.f, den = 0.f;
    const int ch = 2 * t;                 // channels ch, ch+1 (same head)
    const bool head1 = (t >= 128);
    for (int base = start; base < end; base += 256) {
        int m = min(256, end - base);
        if (t < m) {
            int s = g_esrc[base + t];
            float e0 = g_al1s[s * 2 + 0] + ad0; e0 = e0 > 0.f ? e0 : 0.2f * e0;
            float e1 = g_al1s[s * 2 + 1] + ad1; e1 = e1 > 0.f ? e1 : 0.2f * e1;
            sw0[t] = __expf(e0);
            sw1[t] = __expf(e1);
            ss[t] = s;
        }
        __syncthreads();
        for (int j = 0; j < m; j++) {
            int s = ss[j];
            float w = head1 ? sw1[j] : sw0[j];
            float2 hv = *(const float2*)&h[(size_t)s * D2 + ch];
            accx += w * hv.x;
            accy += w * hv.y;
            den += w;
        }
        __syncthreads();
    }
    float rden = 1.f / (den + 1e-16f);
    float2 bb = *(const float2*)&bias[ch];
    float o0 = accx * rden + bb.x;
    float o1 = accy * rden + bb.y;
    o0 = o0 > 0.f ? o0 : 0.f;
    o1 = o1 > 0.f ? o1 : 0.f;
    // tf32-round: out1 feeds only gemm2's A operand
    *(float2*)&out[(size_t)d * D2 + ch] = make_float2(f2tf32f(o0), f2tf32f(o1));
}

__global__ void gat2_agg(const float* __restrict__ bias,  // b2[512]
                         float* __restrict__ out)         // d_out (relu applied)
{
    const float* h = g_g2;
    int d = blockIdx.x, t = threadIdx.x;
    __shared__ float sw[256];
    __shared__ int   ss[256];
    int start = g_off[d], end = g_off[d + 1];
    float ad = g_al2d[d];
    float accx = 0.f, accy = 0.f, den = 0.f;
    const int ch = 2 * t;
    for (int base = start; base < end; base += 256) {
        int m = min(256, end - base);
        if (t < m) {
            int s = g_esrc[base + t];
            float e = g_al2s[s] + ad; e = e > 0.f ? e : 0.2f * e;
            sw[t] = __expf(e);
            ss[t] = s;
        }
        __syncthreads();
        for (int j = 0; j < m; j++) {
            int s = ss[j];
            float w = sw[j];
            float2 hv = *(const float2*)&h[(size_t)s * D2 + ch];
            accx += w * hv.x;
            accy += w * hv.y;
            den += w;
        }
        __syncthreads();
    }
    float rden = 1.f / (den + 1e-16f);
    float2 bb = *(const float2*)&bias[ch];
    float o0 = accx * rden + bb.x;
    float o1 = accy * rden + bb.y;
    o0 = o0 > 0.f ? o0 : 0.f;
    o1 = o1 > 0.f ? o1 : 0.f;
    *(float2*)&out[(size_t)d * D2 + ch] = make_float2(o0, o1);
}

// ------------------------------- launch ---------------------------------------
extern "C" void kernel_launch(void* const* d_in, const int* in_sizes, int n_in,
                              void* d_out, int out_size)
{
    const float* x     = (const float*)d_in[0];
    const int*   adj   = (const int*)d_in[1];     // int32 (JAX x64 disabled)
    const float* W_fc  = (const float*)d_in[2];
    const float* b_fc  = (const float*)d_in[3];
    const float* W1    = (const float*)d_in[4];
    const float* a1s   = (const float*)d_in[5];
    const float* a1d   = (const float*)d_in[6];
    const float* b1    = (const float*)d_in[7];
    const float* W2    = (const float*)d_in[8];
    const float* a2s   = (const float*)d_in[9];
    const float* a2d   = (const float*)d_in[10];
    const float* b2    = (const float*)d_in[11];
    float*       out   = (float*)d_out;

    // CSR build + logit zeroing
    zero_kernel<<<64, 256>>>();
    hist_kernel<<<(E_TOT / 4 + 255) / 256, 256>>>(adj);
    scan_kernel<<<1, 1024>>>();
    scatter_kernel<<<(E_TOT / 4 + 255) / 256, 256>>>(adj);

    // tf32 pre-rounding of GEMM operands
    round_copy<<<(N_NODES * H1 / 4 + 255) / 256, 256>>>(x, 4, N_NODES * H1 / 4);
    round_copy<<<(H1 * H1 / 4 + 255) / 256, 256>>>(W_fc, 5, H1 * H1 / 4);
    round_copy<<<(H1 * D2 / 4 + 255) / 256, 256>>>(W1, 6, H1 * D2 / 4);
    round_copy<<<(D2 * D2 / 4 + 255) / 256, 256>>>(W2, 7, D2 * D2 / 4);

    // fc: g_h0 = tf32(relu(xr @ W_fc + b_fc))   [16384,256]
    gemm_tf32<1, 0, 1><<<dim3(H1 / 128, N_NODES / 128), 256>>>(
        4, 5, b_fc, 0, nullptr, nullptr, N_NODES, H1, H1);
    // gat1 features: g_g1 = g_h0 @ W1           [16384,512]  (+ fused al1)
    gemm_tf32<0, 1, 0><<<dim3(D2 / 128, N_NODES / 128), 256>>>(
        0, 6, nullptr, 1, a1s, a1d, N_NODES, D2, H1);
    gat1_agg<<<N_NODES, 256>>>(b1);

    // gat2 features: g_g2 = g_out1 @ W2         [16384,512]  (+ fused al2)
    gemm_tf32<0, 2, 0><<<dim3(D2 / 128, N_NODES / 128), 256>>>(
        2, 7, nullptr, 3, a2s, a2d, N_NODES, D2, D2);
    gat2_agg<<<N_NODES, 256>>>(b2, out);
}

// round 17
// speedup vs baseline: 1.0548x; 1.0548x over previous
#include <cuda_runtime.h>
#include <cuda_bf16.h>
#include <cstdint>

#define N_NODES 16384
#define E_RAW   262144
#define E_TOT   (E_RAW + N_NODES)   // 278528 with self loops
#define H1      256
#define D2      512                  // 2*H1 = gat1 out channels = gat2 channels

// ---------------- scratch (device globals; no allocation allowed) -------------
__device__ float g_h0  [N_NODES * H1];   // fc output (relu, tf32-rounded)
__device__ float g_g1  [N_NODES * D2];   // gat1 pre-agg features (fp32)
__device__ float g_out1[N_NODES * D2];   // gat1 output (relu, tf32-rounded)
__device__ float g_g2  [N_NODES * D2];   // gat2 pre-agg features (fp32)
__device__ float g_wfcr[H1 * H1];        // tf32-rounded W_fc
__device__ float g_w1r [H1 * D2];        // tf32-rounded W1
__device__ float g_w2r [D2 * D2];        // tf32-rounded W2
__device__ float g_al1s[N_NODES * 2];
__device__ float g_al1d[N_NODES * 2];
__device__ float g_al2s[N_NODES];
__device__ float g_al2d[N_NODES];
__device__ int   g_deg [N_NODES];
__device__ int   g_cur [N_NODES];
__device__ int   g_off [N_NODES + 1];
__device__ int   g_esrc[E_TOT];

__device__ __forceinline__ float* buf_sel(int id) {
    switch (id) {
        case 0: return g_h0;
        case 1: return g_g1;
        case 2: return g_out1;
        case 3: return g_g2;
        case 5: return g_wfcr;
        case 6: return g_w1r;
        case 7: return g_w2r;
    }
    return nullptr;
}

__device__ __forceinline__ float f2tf32f(float x) {
    uint32_t u;
    asm("cvt.rna.tf32.f32 %0, %1;" : "=r"(u) : "f"(x));
    return __uint_as_float(u);
}
__device__ __forceinline__ uint32_t f2tf32(float x) {
    uint32_t u;
    asm("cvt.rna.tf32.f32 %0, %1;" : "=r"(u) : "f"(x));
    return u;
}

// ------------------------------- CSR build -----------------------------------
__global__ void zero_kernel() {
    int i = blockIdx.x * blockDim.x + threadIdx.x;
    if (i < N_NODES) {
        g_deg[i] = 0; g_cur[i] = 0;
        g_al1s[2 * i] = 0.f; g_al1s[2 * i + 1] = 0.f;
        g_al1d[2 * i] = 0.f; g_al1d[2 * i + 1] = 0.f;
        g_al2s[i] = 0.f;     g_al2d[i] = 0.f;
    }
}

// adj is int32: adj[0..E_RAW) = src, adj[E_RAW..2*E_RAW) = dst
__global__ void hist_kernel(const int* __restrict__ adj) {
    int i = blockIdx.x * blockDim.x + threadIdx.x;
    if (i >= E_TOT) return;
    int dst = (i < E_RAW) ? adj[E_RAW + i] : (i - E_RAW);
    atomicAdd(&g_deg[dst], 1);
}

__global__ void scan_kernel() {
    __shared__ int partial[1024];
    int t = threadIdx.x;
    int base = t * 16;
    int local[16];
    int s = 0;
#pragma unroll
    for (int i = 0; i < 16; i++) { local[i] = s; s += g_deg[base + i]; }
    partial[t] = s;
    __syncthreads();
    for (int off = 1; off < 1024; off <<= 1) {
        int v = (t >= off) ? partial[t - off] : 0;
        __syncthreads();
        partial[t] += v;
        __syncthreads();
    }
    int pre = (t == 0) ? 0 : partial[t - 1];
#pragma unroll
    for (int i = 0; i < 16; i++) g_off[base + i] = pre + local[i];
    if (t == 1023) g_off[N_NODES] = partial[1023];
}

__global__ void scatter_kernel(const int* __restrict__ adj) {
    int i = blockIdx.x * blockDim.x + threadIdx.x;
    if (i >= E_TOT) return;
    int src, dst;
    if (i < E_RAW) { src = adj[i]; dst = adj[E_RAW + i]; }
    else           { src = i - E_RAW;  dst = i - E_RAW; }
    int pos = g_off[dst] + atomicAdd(&g_cur[dst], 1);
    g_esrc[pos] = src;
}

// --------------------------- tf32 weight pre-rounding -------------------------
__global__ void round_copy(const float* __restrict__ src, int dst_sel, int n4) {
    float* dst = buf_sel(dst_sel);
    int i = blockIdx.x * blockDim.x + threadIdx.x;
    if (i >= n4) return;
    float4 v = ((const float4*)src)[i];
    v.x = f2tf32f(v.x); v.y = f2tf32f(v.y);
    v.z = f2tf32f(v.z); v.w = f2tf32f(v.w);
    ((float4*)dst)[i] = v;
}

// --------------------------- TF32 tensor-core GEMM ----------------------------
// C[M,N] = A[M,K] * B[K,N], row-major. B always pre-rounded tf32.
// CVT_A: round A tiles in-kernel (only needed when A = external x).
// CTA tile 128x128, 8 warps, warp tile 64x32, mma.sync m16n8k8 tf32,
// K-chunk 32, register-prefetch double buffering.
// AL_MODE 1: fused gat1 logit partials (2 heads). AL_MODE 2: gat2 (1 head).
#define AS_STRIDE 36
#define BS_STRIDE 136

template <int RELU_BIAS, int AL_MODE, int ROUND_OUT, int CVT_A>
__global__ __launch_bounds__(256) void gemm_tf32(
    const float* __restrict__ A_ext, int a_sel, int b_sel,
    const float* __restrict__ bias, int c_sel,
    const float* __restrict__ a_s, const float* __restrict__ a_d,
    int M, int N, int K)
{
    const float* A = (a_sel < 0) ? A_ext : buf_sel(a_sel);
    const float* B = buf_sel(b_sel);
    float* C = buf_sel(c_sel);

    __shared__ float As[128 * AS_STRIDE];   // [m][k32], pad->36
    __shared__ float Bs[32 * BS_STRIDE];    // [k32][n128], pad->136

    const int tid  = threadIdx.x;
    const int lane = tid & 31;
    const int wid  = tid >> 5;
    const int q = lane >> 2;     // 0..7
    const int r = lane & 3;      // 0..3
    const int wm = (wid >> 2) * 64;   // warp m offset: 0 or 64
    const int wn = (wid & 3) * 32;    // warp n offset: 0,32,64,96

    const int mBase = blockIdx.y * 128, nBase = blockIdx.x * 128;

    float c[4][4][4];
#pragma unroll
    for (int i = 0; i < 4; i++)
#pragma unroll
        for (int j = 0; j < 4; j++)
#pragma unroll
            for (int u = 0; u < 4; u++) c[i][j][u] = 0.f;

    float4 pa[4], pb[4];
#pragma unroll
    for (int l = 0; l < 4; l++) {
        int idx = tid + l * 256;
        int row = idx >> 3, c4 = idx & 7;
        pa[l] = *(const float4*)&A[(size_t)(mBase + row) * K + c4 * 4];
        int kk = idx >> 5, n4 = idx & 31;
        pb[l] = *(const float4*)&B[(size_t)kk * N + nBase + n4 * 4];
    }

    for (int k0 = 0; k0 < K; k0 += 32) {
#pragma unroll
        for (int l = 0; l < 4; l++) {
            int idx = tid + l * 256;
            int row = idx >> 3, c4 = idx & 7;
            float* ap = &As[row * AS_STRIDE + c4 * 4];
            if (CVT_A) {
                ap[0] = f2tf32f(pa[l].x);
                ap[1] = f2tf32f(pa[l].y);
                ap[2] = f2tf32f(pa[l].z);
                ap[3] = f2tf32f(pa[l].w);
            } else {
                *(float4*)ap = pa[l];
            }
            int kk = idx >> 5, n4 = idx & 31;
            *(float4*)&Bs[kk * BS_STRIDE + n4 * 4] = pb[l];
        }
        __syncthreads();

        if (k0 + 32 < K) {
#pragma unroll
            for (int l = 0; l < 4; l++) {
                int idx = tid + l * 256;
                int row = idx >> 3, c4 = idx & 7;
                pa[l] = *(const float4*)&A[(size_t)(mBase + row) * K + k0 + 32 + c4 * 4];
                int kk = idx >> 5, n4 = idx & 31;
                pb[l] = *(const float4*)&B[(size_t)(k0 + 32 + kk) * N + nBase + n4 * 4];
            }
        }

#pragma unroll
        for (int kk8 = 0; kk8 < 4; kk8++) {
            const int kb = kk8 * 8;
            uint32_t a[4][4], b[4][2];
#pragma unroll
            for (int i = 0; i < 4; i++) {
                int row = wm + i * 16 + q;
                a[i][0] = __float_as_uint(As[(row)     * AS_STRIDE + kb + r]);
                a[i][1] = __float_as_uint(As[(row + 8) * AS_STRIDE + kb + r]);
                a[i][2] = __float_as_uint(As[(row)     * AS_STRIDE + kb + r + 4]);
                a[i][3] = __float_as_uint(As[(row + 8) * AS_STRIDE + kb + r + 4]);
            }
#pragma unroll
            for (int j = 0; j < 4; j++) {
                int col = wn + j * 8 + q;
                b[j][0] = __float_as_uint(Bs[(kb + r)     * BS_STRIDE + col]);
                b[j][1] = __float_as_uint(Bs[(kb + r + 4) * BS_STRIDE + col]);
            }
#pragma unroll
            for (int i = 0; i < 4; i++)
#pragma unroll
                for (int j = 0; j < 4; j++) {
                    asm volatile(
                        "mma.sync.aligned.m16n8k8.row.col.f32.tf32.tf32.f32 "
                        "{%0,%1,%2,%3}, {%4,%5,%6,%7}, {%8,%9}, {%0,%1,%2,%3};"
                        : "+f"(c[i][j][0]), "+f"(c[i][j][1]),
                          "+f"(c[i][j][2]), "+f"(c[i][j][3])
                        : "r"(a[i][0]), "r"(a[i][1]), "r"(a[i][2]), "r"(a[i][3]),
                          "r"(b[j][0]), "r"(b[j][1]));
                }
        }
        __syncthreads();
    }

    // epilogue (+ optional fused attention-logit partial sums)
    float ps[4][2], pd[4][2];
    if (AL_MODE) {
#pragma unroll
        for (int i = 0; i < 4; i++) {
            ps[i][0] = ps[i][1] = 0.f;
            pd[i][0] = pd[i][1] = 0.f;
        }
    }

#pragma unroll
    for (int i = 0; i < 4; i++) {
        int row0 = mBase + wm + i * 16 + q;
#pragma unroll
        for (int j = 0; j < 4; j++) {
            int col = nBase + wn + j * 8 + 2 * r;
            float v0 = c[i][j][0], v1 = c[i][j][1];
            float v2 = c[i][j][2], v3 = c[i][j][3];
            if (RELU_BIAS) {
                float bb0 = bias[col], bb1 = bias[col + 1];
                v0 += bb0; v1 += bb1; v2 += bb0; v3 += bb1;
                v0 = v0 > 0.f ? v0 : 0.f; v1 = v1 > 0.f ? v1 : 0.f;
                v2 = v2 > 0.f ? v2 : 0.f; v3 = v3 > 0.f ? v3 : 0.f;
            }
            if (AL_MODE) {
                float as0 = a_s[col], as1 = a_s[col + 1];
                float ad0 = a_d[col], ad1 = a_d[col + 1];
                ps[i][0] += v0 * as0 + v1 * as1;
                pd[i][0] += v0 * ad0 + v1 * ad1;
                ps[i][1] += v2 * as0 + v3 * as1;
                pd[i][1] += v2 * ad0 + v3 * ad1;
            }
            if (ROUND_OUT) {
                v0 = f2tf32f(v0); v1 = f2tf32f(v1);
                v2 = f2tf32f(v2); v3 = f2tf32f(v3);
            }
            *(float2*)&C[(size_t)row0 * N + col]       = make_float2(v0, v1);
            *(float2*)&C[(size_t)(row0 + 8) * N + col] = make_float2(v2, v3);
        }
    }

    if (AL_MODE) {
#pragma unroll
        for (int i = 0; i < 4; i++) {
#pragma unroll
            for (int half = 0; half < 2; half++) {
                float s = ps[i][half], dd = pd[i][half];
                s  += __shfl_xor_sync(0xffffffffu, s, 1);
                s  += __shfl_xor_sync(0xffffffffu, s, 2);
                dd += __shfl_xor_sync(0xffffffffu, dd, 1);
                dd += __shfl_xor_sync(0xffffffffu, dd, 2);
                if (r == 0) {
                    int row = mBase + wm + i * 16 + q + half * 8;
                    if (AL_MODE == 1) {
                        int head = ((nBase + wn) >> 8) & 1;
                        atomicAdd(&g_al1s[row * 2 + head], s);
                        atomicAdd(&g_al1d[row * 2 + head], dd);
                    } else {
                        atomicAdd(&g_al2s[row], s);
                        atomicAdd(&g_al2d[row], dd);
                    }
                }
            }
        }
    }
}

// --------------------------- GAT aggregation ----------------------------------
// Softmax without max subtraction: self-loops guarantee nonempty segments and
// glorot-scale logits are O(+-5) -> exp cannot overflow; alpha identical.
// One CTA (256 threads) per dst node; thread t owns channels 2t, 2t+1.
__global__ void gat1_agg(const float* __restrict__ bias)  // b1[512] -> g_out1
{
    const float* h = g_g1;
    float* out = g_out1;
    int d = blockIdx.x, t = threadIdx.x;
    __shared__ float sw0[256], sw1[256];
    __shared__ int   ss[256];
    int start = g_off[d], end = g_off[d + 1];
    float ad0 = g_al1d[d * 2 + 0], ad1 = g_al1d[d * 2 + 1];
    float accx = 0.f, accy = 0.f, den = 0.f;
    const int ch = 2 * t;                 // channels ch, ch+1 (same head)
    const bool head1 = (t >= 128);
    for (int base = start; base < end; base += 256) {
        int m = min(256, end - base);
        if (t < m) {
            int s = g_esrc[base + t];
            float e0 = g_al1s[s * 2 + 0] + ad0; e0 = e0 > 0.f ? e0 : 0.2f * e0;
            float e1 = g_al1s[s * 2 + 1] + ad1; e1 = e1 > 0.f ? e1 : 0.2f * e1;
            sw0[t] = __expf(e0);
            sw1[t] = __expf(e1);
            ss[t] = s;
        }
        __syncthreads();
        for (int j = 0; j < m; j++) {
            int s = ss[j];
            float w = head1 ? sw1[j] : sw0[j];
            float2 hv = *(const float2*)&h[(size_t)s * D2 + ch];
            accx += w * hv.x;
            accy += w * hv.y;
            den += w;
        }
        __syncthreads();
    }
    float rden = 1.f / (den + 1e-16f);
    float2 bb = *(const float2*)&bias[ch];
    float o0 = accx * rden + bb.x;
    float o1 = accy * rden + bb.y;
    o0 = o0 > 0.f ? o0 : 0.f;
    o1 = o1 > 0.f ? o1 : 0.f;
    // tf32-round: out1 feeds only gemm3's A operand
    *(float2*)&out[(size_t)d * D2 + ch] = make_float2(f2tf32f(o0), f2tf32f(o1));
}

__global__ void gat2_agg(const float* __restrict__ bias,  // b2[512]
                         float* __restrict__ out)         // d_out (relu applied)
{
    const float* h = g_g2;
    int d = blockIdx.x, t = threadIdx.x;
    __shared__ float sw[256];
    __shared__ int   ss[256];
    int start = g_off[d], end = g_off[d + 1];
    float ad = g_al2d[d];
    float accx = 0.f, accy = 0.f, den = 0.f;
    const int ch = 2 * t;
    for (int base = start; base < end; base += 256) {
        int m = min(256, end - base);
        if (t < m) {
            int s = g_esrc[base + t];
            float e = g_al2s[s] + ad; e = e > 0.f ? e : 0.2f * e;
            sw[t] = __expf(e);
            ss[t] = s;
        }
        __syncthreads();
        for (int j = 0; j < m; j++) {
            int s = ss[j];
            float w = sw[j];
            float2 hv = *(const float2*)&h[(size_t)s * D2 + ch];
            accx += w * hv.x;
            accy += w * hv.y;
            den += w;
        }
        __syncthreads();
    }
    float rden = 1.f / (den + 1e-16f);
    float2 bb = *(const float2*)&bias[ch];
    float o0 = accx * rden + bb.x;
    float o1 = accy * rden + bb.y;
    o0 = o0 > 0.f ? o0 : 0.f;
    o1 = o1 > 0.f ? o1 : 0.f;
    *(float2*)&out[(size_t)d * D2 + ch] = make_float2(o0, o1);
}

// ------------------------------- launch ---------------------------------------
extern "C" void kernel_launch(void* const* d_in, const int* in_sizes, int n_in,
                              void* d_out, int out_size)
{
    const float* x     = (const float*)d_in[0];
    const int*   adj   = (const int*)d_in[1];     // int32 (JAX x64 disabled)
    const float* W_fc  = (const float*)d_in[2];
    const float* b_fc  = (const float*)d_in[3];
    const float* W1    = (const float*)d_in[4];
    const float* a1s   = (const float*)d_in[5];
    const float* a1d   = (const float*)d_in[6];
    const float* b1    = (const float*)d_in[7];
    const float* W2    = (const float*)d_in[8];
    const float* a2s   = (const float*)d_in[9];
    const float* a2d   = (const float*)d_in[10];
    const float* b2    = (const float*)d_in[11];
    float*       out   = (float*)d_out;

    // CSR build + logit zeroing
    zero_kernel<<<64, 256>>>();
    hist_kernel<<<(E_TOT + 255) / 256, 256>>>(adj);
    scan_kernel<<<1, 1024>>>();
    scatter_kernel<<<(E_TOT + 255) / 256, 256>>>(adj);

    // tf32 pre-rounding of weights (cheap; features rounded at producers)
    round_copy<<<(H1 * H1 / 4 + 255) / 256, 256>>>(W_fc, 5, H1 * H1 / 4);
    round_copy<<<(H1 * D2 / 4 + 255) / 256, 256>>>(W1, 6, H1 * D2 / 4);
    round_copy<<<(D2 * D2 / 4 + 255) / 256, 256>>>(W2, 7, D2 * D2 / 4);

    // fc: g_h0 = tf32(relu(x @ W_fc + b_fc))   [16384,256]  (CVT_A for x)
    gemm_tf32<1, 0, 1, 1><<<dim3(H1 / 128, N_NODES / 128), 256>>>(
        x, -1, 5, b_fc, 0, nullptr, nullptr, N_NODES, H1, H1);
    // gat1 features: g_g1 = g_h0 @ W1          [16384,512]  (+ fused al1)
    gemm_tf32<0, 1, 0, 0><<<dim3(D2 / 128, N_NODES / 128), 256>>>(
        nullptr, 0, 6, nullptr, 1, a1s, a1d, N_NODES, D2, H1);
    gat1_agg<<<N_NODES, 256>>>(b1);

    // gat2 features: g_g2 = g_out1 @ W2        [16384,512]  (+ fused al2)
    gemm_tf32<0, 2, 0, 0><<<dim3(D2 / 128, N_NODES / 128), 256>>>(
        nullptr, 2, 7, nullptr, 3, a2s, a2d, N_NODES, D2, D2);
    gat2_agg<<<N_NODES, 256>>>(b2, out);
}